// round 13
// baseline (speedup 1.0000x reference)
#include <cuda_runtime.h>
#include <math.h>
#include <stdint.h>

#define B 16
#define M 2048
#define BPB 8                   // src-blocks per batch (256 src each)
#define DSPLIT 16               // dest slices
#define DLEN (M / DSPLIT)       // 128 dest points per slice
#define BLKS_PER_BATCH (BPB * DSPLIT)   // 128
#define NBLK (B * BLKS_PER_BATCH)       // 2048 blocks
#define NTHREADS 128
#define ITERS 10
#define MSE_THRESH 1e-5f

// -------- persistent device state (no allocations allowed) --------
__device__ float  g_R[B][9];
__device__ float  g_t[B][3];
__device__ float  g_mse[B];
__device__ int    g_done[B];
__device__ float2 g_pair[B][M][DSPLIT];  // {partial best d2, idx bits}
__device__ float4 g_P1[B][M];            // scratch pass1/pass2
__device__ float4 g_P2[B][M];
__device__ int    g_six[B][M];
__device__ int    g_cnt[ITERS][B];       // per-iteration arrival counters

// K=3 contraction as dot_general lowers: ascending-k fma chain, exact first product
__device__ __forceinline__ float dot3_ref(float a0, float a1, float a2,
                                          float b0, float b1, float b2) {
    return fmaf(a2, b2, fmaf(a1, b1, __fmul_rn(a0, b0)));
}
// (v*v).sum: rounded products, sequential adds, no fma
__device__ __forceinline__ float sqsum3(float x, float y, float z) {
    return __fadd_rn(__fadd_rn(__fmul_rn(x, x), __fmul_rn(y, y)), __fmul_rn(z, z));
}
// pairwise balanced tree over 8 lanes (FROZEN: R7 order)
__device__ __forceinline__ float tree8(float x) {
    x = __fadd_rn(x, __shfl_down_sync(0xffffffffu, x, 1));
    x = __fadd_rn(x, __shfl_down_sync(0xffffffffu, x, 2));
    x = __fadd_rn(x, __shfl_down_sync(0xffffffffu, x, 4));
    return x;
}
__device__ __forceinline__ unsigned long long pack2(float v) {
    unsigned int u = __float_as_uint(v);
    return ((unsigned long long)u << 32) | (unsigned long long)u;
}
// packed f32x2: per-lane IEEE fp32, bit-identical to scalar sequence
__device__ __forceinline__ unsigned long long mul2(unsigned long long a, unsigned long long b) {
    unsigned long long d; asm("mul.rn.f32x2 %0, %1, %2;" : "=l"(d) : "l"(a), "l"(b)); return d;
}
__device__ __forceinline__ unsigned long long fma2(unsigned long long a, unsigned long long b,
                                                   unsigned long long c) {
    unsigned long long d; asm("fma.rn.f32x2 %0, %1, %2, %3;" : "=l"(d) : "l"(a), "l"(b), "l"(c)); return d;
}
__device__ __forceinline__ unsigned long long add2(unsigned long long a, unsigned long long b) {
    unsigned long long d; asm("add.rn.f32x2 %0, %1, %2;" : "=l"(d) : "l"(a), "l"(b)); return d;
}
__device__ __forceinline__ float lo32(unsigned long long v) { return __uint_as_float((unsigned int)v); }
__device__ __forceinline__ float hi32(unsigned long long v) { return __uint_as_float((unsigned int)(v >> 32)); }

__global__ void init_kernel() {
    int i = threadIdx.x;
    if (i < B) {
        #pragma unroll
        for (int k = 0; k < 9; k++) g_R[i][k] = (k % 4 == 0) ? 1.0f : 0.0f;
        g_t[i][0] = 0.f; g_t[i][1] = 0.f; g_t[i][2] = 0.f;
        g_mse[i] = 0.f;
        g_done[i] = 0;
    }
    for (int k = i; k < ITERS * B; k += 256) ((int*)g_cnt)[k] = 0;
}

// -------- fused NN + (last block) update --------
__global__ void __launch_bounds__(NTHREADS, 8)
nn_update_kernel(const float* __restrict__ src,
                 const float* __restrict__ dest, int it) {
    __shared__ ulonglong2 qP[DLEN / 2];   // {x pair, y pair}
    __shared__ ulonglong2 qQ[DLEN / 2];   // {z pair, qq pair}
    __shared__ float smu[8];
    __shared__ int   s_last;

    const int bid = blockIdx.x;
    const int b   = bid / BLKS_PER_BATCH;
    const int rem = bid % BLKS_PER_BATCH;
    const int blk = rem / DSPLIT;
    const int d   = rem % DSPLIT;
    if (g_done[b]) return;

    const int tid  = threadIdx.x;
    const int jof  = d * DLEN;
    const float* db = dest + (size_t)b * 3 * M;
    const float* sb = src  + (size_t)b * 3 * M;

    {   // stage dest slice (pair-packed)
        int jj = jof + tid;
        float x = db[jj], y = db[M + jj], z = db[2 * M + jj];
        float qq = sqsum3(x, y, z);
        float* fP = (float*)qP; float* fQ = (float*)qQ;
        int p = tid >> 1, o = tid & 1;
        fP[4 * p + o] = x;  fP[4 * p + 2 + o] = y;
        fQ[4 * p + o] = z;  fQ[4 * p + 2 + o] = qq;
    }

    float R0 = g_R[b][0], R1 = g_R[b][1], R2 = g_R[b][2];
    float R3 = g_R[b][3], R4 = g_R[b][4], R5 = g_R[b][5];
    float R6 = g_R[b][6], R7 = g_R[b][7], R8 = g_R[b][8];
    float t0 = g_t[b][0], t1 = g_t[b][1], t2 = g_t[b][2];

    __syncthreads();

    // two src points per thread
    const int mA = blk * 256 + tid;
    const int mB = mA + 128;
    const float INF = __int_as_float(0x7f800000);
    unsigned long long pxA, pyA, pzA, ppA, pxB, pyB, pzB, ppB;
    {
        float sx = sb[mA], sy = sb[M + mA], sz = sb[2 * M + mA];
        float px = __fadd_rn(dot3_ref(sx, sy, sz, R0, R1, R2), t0);
        float py = __fadd_rn(dot3_ref(sx, sy, sz, R3, R4, R5), t1);
        float pz = __fadd_rn(dot3_ref(sx, sy, sz, R6, R7, R8), t2);
        float pp = sqsum3(px, py, pz);
        pxA = pack2(px); pyA = pack2(py); pzA = pack2(pz); ppA = pack2(pp);
    }
    {
        float sx = sb[mB], sy = sb[M + mB], sz = sb[2 * M + mB];
        float px = __fadd_rn(dot3_ref(sx, sy, sz, R0, R1, R2), t0);
        float py = __fadd_rn(dot3_ref(sx, sy, sz, R3, R4, R5), t1);
        float pz = __fadd_rn(dot3_ref(sx, sy, sz, R6, R7, R8), t2);
        float pp = sqsum3(px, py, pz);
        pxB = pack2(px); pyB = pack2(py); pzB = pack2(pz); ppB = pack2(pp);
    }
    const unsigned long long n2 = pack2(-2.0f);

    float a0 = INF, a1 = INF, a2 = INF, a3 = INF;   // src A accumulators
    float c0 = INF, c1 = INF, c2 = INF, c3 = INF;   // src B accumulators
    int   ia0 = 0, ia1 = 0, ia2 = 0, ia3 = 0;
    int   ic0 = 0, ic1 = 0, ic2 = 0, ic3 = 0;

    #pragma unroll 8
    for (int j2 = 0; j2 < DLEN / 2; j2 += 2) {
        ulonglong2 A0 = qP[j2],     B0 = qQ[j2];
        ulonglong2 A1 = qP[j2 + 1], B1 = qQ[j2 + 1];
        int base = 2 * j2;
        // src A
        {
            unsigned long long dd0 = fma2(n2, fma2(pzA, B0.x, fma2(pyA, A0.y, mul2(pxA, A0.x))), add2(ppA, B0.y));
            unsigned long long dd1 = fma2(n2, fma2(pzA, B1.x, fma2(pyA, A1.y, mul2(pxA, A1.x))), add2(ppA, B1.y));
            float d0 = lo32(dd0), d1 = hi32(dd0), d2 = lo32(dd1), d3 = hi32(dd1);
            if (d0 < a0) { a0 = d0; ia0 = base; }
            if (d1 < a1) { a1 = d1; ia1 = base + 1; }
            if (d2 < a2) { a2 = d2; ia2 = base + 2; }
            if (d3 < a3) { a3 = d3; ia3 = base + 3; }
        }
        // src B
        {
            unsigned long long dd0 = fma2(n2, fma2(pzB, B0.x, fma2(pyB, A0.y, mul2(pxB, A0.x))), add2(ppB, B0.y));
            unsigned long long dd1 = fma2(n2, fma2(pzB, B1.x, fma2(pyB, A1.y, mul2(pxB, A1.x))), add2(ppB, B1.y));
            float d0 = lo32(dd0), d1 = hi32(dd0), d2 = lo32(dd1), d3 = hi32(dd1);
            if (d0 < c0) { c0 = d0; ic0 = base; }
            if (d1 < c1) { c1 = d1; ic1 = base + 1; }
            if (d2 < c2) { c2 = d2; ic2 = base + 2; }
            if (d3 < c3) { c3 = d3; ic3 = base + 3; }
        }
    }

    {   // merge src A (first-min tie rule)
        float best = a0; int bi = ia0;
        if (a1 < best || (a1 == best && ia1 < bi)) { best = a1; bi = ia1; }
        if (a2 < best || (a2 == best && ia2 < bi)) { best = a2; bi = ia2; }
        if (a3 < best || (a3 == best && ia3 < bi)) { best = a3; bi = ia3; }
        g_pair[b][mA][d] = make_float2(best, __int_as_float(jof + bi));
    }
    {   // merge src B
        float best = c0; int bi = ic0;
        if (c1 < best || (c1 == best && ic1 < bi)) { best = c1; bi = ic1; }
        if (c2 < best || (c2 == best && ic2 < bi)) { best = c2; bi = ic2; }
        if (c3 < best || (c3 == best && ic3 < bi)) { best = c3; bi = ic3; }
        g_pair[b][mB][d] = make_float2(best, __int_as_float(jof + bi));
    }

    // ---- arrival protocol: last block of this batch runs the update ----
    __threadfence();                 // release this thread's g_pair writes
    __syncthreads();
    if (tid == 0) {
        int c = atomicAdd(&g_cnt[it][b], 1);
        s_last = (c == BLKS_PER_BATCH - 1);
        if (s_last) __threadfence(); // acquire side
    }
    __syncthreads();
    if (!s_last) return;

    // ================= UPDATE (one block per batch) =================
    // pass1: merge slice partials + phase-A element values (order-free)
    for (int m = tid; m < M; m += NTHREADS) {
        const float4* p4 = (const float4*)&g_pair[b][m][0];   // 8 x float4
        float4 f = p4[0];
        float best = f.x; int bi = __float_as_int(f.y);
        if (f.z < best) { best = f.z; bi = __float_as_int(f.w); }
        #pragma unroll
        for (int k = 1; k < 8; k++) {
            f = p4[k];
            if (f.x < best) { best = f.x; bi = __float_as_int(f.y); }
            if (f.z < best) { best = f.z; bi = __float_as_int(f.w); }
        }
        float nn = fmaxf(best, 0.0f);
        float w  = (sqrtf(nn) < 3.0f) ? 1.0f : 0.0f;
        float qx = db[bi], qy = db[M + bi], qz = db[2 * M + bi];
        g_P1[b][m] = make_float4(w,
                                 __fmul_rn(w, sb[m]),
                                 __fmul_rn(w, sb[M + m]),
                                 __fmul_rn(w, sb[2 * M + m]));
        g_P2[b][m] = make_float4(__fmul_rn(w, qx),
                                 __fmul_rn(w, qy),
                                 __fmul_rn(w, qz),
                                 nn);
        g_six[b][m] = bi;
    }
    __syncthreads();

    // phase A: FROZEN scalar add chains, packed as f32x2 over independent
    // accumulator pairs (per-lane IEEE == scalar chain bitwise)
    if (tid < 32) {
        const int lane = tid;
        unsigned long long accA = 0, accB = 0, accC = 0, accD = 0;  // (0.0f,0.0f) pairs
        if (lane < 8) {
            const ulonglong2* P1u = (const ulonglong2*)&g_P1[b][0];
            const ulonglong2* P2u = (const ulonglong2*)&g_P2[b][0];
            #pragma unroll 8
            for (int k = 0; k < M / 8; k++) {
                int m = lane + 8 * k;
                ulonglong2 u1 = P1u[m];   // {(w,wsx),(wsy,wsz)}
                ulonglong2 u2 = P2u[m];   // {(wqx,wqy),(wqz,nn)}
                accA = add2(accA, u1.x);  // (pw, ps0)
                accB = add2(accB, u1.y);  // (ps1, ps2)
                accC = add2(accC, u2.x);  // (pq0, pq1)
                accD = add2(accD, u2.y);  // (pq2, pnn)
            }
        }
        float pw  = lo32(accA), ps0 = hi32(accA);
        float ps1 = lo32(accB), ps2 = hi32(accB);
        float pq0 = lo32(accC), pq1 = hi32(accC);
        float pq2 = lo32(accD), pnn = hi32(accD);
        pw  = tree8(pw);
        ps0 = tree8(ps0); ps1 = tree8(ps1); ps2 = tree8(ps2);
        pq0 = tree8(pq0); pq1 = tree8(pq1); pq2 = tree8(pq2);
        pnn = tree8(pnn);
        if (lane == 0) {
            float wsum = __fadd_rn(pw, 1e-8f);
            smu[0] = __fdiv_rn(ps0, wsum);
            smu[1] = __fdiv_rn(ps1, wsum);
            smu[2] = __fdiv_rn(ps2, wsum);
            smu[3] = __fdiv_rn(pq0, wsum);
            smu[4] = __fdiv_rn(pq1, wsum);
            smu[5] = __fdiv_rn(pq2, wsum);
            smu[6] = pnn;
        }
    }
    __syncthreads();

    const float ms0 = smu[0], ms1 = smu[1], ms2 = smu[2];
    const float mq0 = smu[3], mq1 = smu[4], mq2 = smu[5];

    // pass2: centered products (order-free)
    for (int m = tid; m < M; m += NTHREADS) {
        float w = g_P1[b][m].x;
        int   j = g_six[b][m];
        g_P1[b][m] = make_float4(__fmul_rn(__fsub_rn(sb[m],         ms0), w),
                                 __fmul_rn(__fsub_rn(sb[M + m],     ms1), w),
                                 __fmul_rn(__fsub_rn(sb[2 * M + m], ms2), w),
                                 0.f);
        g_P2[b][m] = make_float4(__fsub_rn(db[j],         mq0),
                                 __fsub_rn(db[M + j],     mq1),
                                 __fsub_rn(db[2 * M + j], mq2),
                                 0.f);
    }
    __syncthreads();

    if (tid >= 32) return;
    const int lane = tid;

    // phase B: FROZEN fma chains (scalar)
    float h[9] = {0,0,0,0,0,0,0,0,0};
    if (lane < 8) {
        #pragma unroll 4
        for (int k = 0; k < M / 8; k++) {
            int m = lane + 8 * k;
            float4 a = g_P1[b][m];
            float4 c = g_P2[b][m];
            h[0] = fmaf(a.x, c.x, h[0]); h[1] = fmaf(a.x, c.y, h[1]); h[2] = fmaf(a.x, c.z, h[2]);
            h[3] = fmaf(a.y, c.x, h[3]); h[4] = fmaf(a.y, c.y, h[4]); h[5] = fmaf(a.y, c.z, h[5]);
            h[6] = fmaf(a.z, c.x, h[6]); h[7] = fmaf(a.z, c.y, h[7]); h[8] = fmaf(a.z, c.z, h[8]);
        }
    }
    #pragma unroll
    for (int v = 0; v < 9; v++) h[v] = tree8(h[v]);

    if (lane != 0) return;

    // fp32 Jacobi SVD (unchanged from R10-R12)
    float Hf[3][3];
    #pragma unroll
    for (int v = 0; v < 9; v++) Hf[v / 3][v % 3] = h[v];

    float A[3][3];
    #pragma unroll
    for (int i = 0; i < 3; i++)
        #pragma unroll
        for (int j = 0; j < 3; j++)
            A[i][j] = fmaf(Hf[2][i], Hf[2][j], fmaf(Hf[1][i], Hf[1][j], Hf[0][i] * Hf[0][j]));

    const float tr = A[0][0] + A[1][1] + A[2][2];
    const float off_thr = 1e-12f * tr * tr;
    float V[3][3] = {{1,0,0},{0,1,0},{0,0,1}};
    for (int sweep = 0; sweep < 6; sweep++) {
        float off = A[0][1]*A[0][1] + A[0][2]*A[0][2] + A[1][2]*A[1][2];
        if (off <= off_thr) break;
        #pragma unroll
        for (int pi = 0; pi < 3; pi++) {
            int p = (pi == 2) ? 1 : 0;
            int q = (pi == 0) ? 1 : 2;
            float apq = A[p][q];
            if (fabsf(apq) < 1e-30f) continue;
            float theta = (A[q][q] - A[p][p]) / (2.0f * apq);
            float tt = copysignf(1.0f, theta) / (fabsf(theta) + sqrtf(fmaf(theta, theta, 1.0f)));
            float c = rsqrtf(fmaf(tt, tt, 1.0f));
            float s = tt * c;
            #pragma unroll
            for (int k = 0; k < 3; k++) {
                float akp = A[k][p], akq = A[k][q];
                A[k][p] = c * akp - s * akq;
                A[k][q] = s * akp + c * akq;
            }
            #pragma unroll
            for (int k = 0; k < 3; k++) {
                float apk = A[p][k], aqk = A[q][k];
                A[p][k] = c * apk - s * aqk;
                A[q][k] = s * apk + c * aqk;
            }
            #pragma unroll
            for (int k = 0; k < 3; k++) {
                float vkp = V[k][p], vkq = V[k][q];
                V[k][p] = c * vkp - s * vkq;
                V[k][q] = s * vkp + c * vkq;
            }
        }
    }

    float lam[3] = {A[0][0], A[1][1], A[2][2]};
    int idx[3] = {0, 1, 2};
    #pragma unroll
    for (int i = 0; i < 2; i++)
        #pragma unroll
        for (int j = i + 1; j < 3; j++)
            if (lam[idx[j]] > lam[idx[i]]) { int t = idx[i]; idx[i] = idx[j]; idx[j] = t; }

    float detH = Hf[0][0]*(Hf[1][1]*Hf[2][2]-Hf[1][2]*Hf[2][1])
               - Hf[0][1]*(Hf[1][0]*Hf[2][2]-Hf[1][2]*Hf[2][0])
               + Hf[0][2]*(Hf[1][0]*Hf[2][1]-Hf[1][1]*Hf[2][0]);
    float d3 = (detH >= 0.0f) ? 1.0f : -1.0f;

    float coef[3], Vs[3][3];
    #pragma unroll
    for (int r = 0; r < 3; r++) {
        float sv = sqrtf(fmaxf(lam[idx[r]], 0.0f));
        float dr = (r == 2) ? d3 : 1.0f;
        coef[r] = (sv > 1e-20f) ? (dr / sv) : 0.0f;
        #pragma unroll
        for (int k = 0; k < 3; k++) Vs[k][r] = V[k][idx[r]];
    }

    float M2[3][3];
    #pragma unroll
    for (int i = 0; i < 3; i++)
        #pragma unroll
        for (int j = 0; j < 3; j++)
            M2[i][j] = fmaf(Vs[i][2] * coef[2], Vs[j][2],
                       fmaf(Vs[i][1] * coef[1], Vs[j][1],
                            Vs[i][0] * coef[0] * Vs[j][0]));
    float Rf[3][3];
    #pragma unroll
    for (int i = 0; i < 3; i++)
        #pragma unroll
        for (int j = 0; j < 3; j++)
            Rf[i][j] = fmaf(M2[i][2], Hf[j][2],
                       fmaf(M2[i][1], Hf[j][1],
                            M2[i][0] * Hf[j][0]));

    float tn[3];
    tn[0] = __fsub_rn(mq0, dot3_ref(ms0, ms1, ms2, Rf[0][0], Rf[0][1], Rf[0][2]));
    tn[1] = __fsub_rn(mq1, dot3_ref(ms0, ms1, ms2, Rf[1][0], Rf[1][1], Rf[1][2]));
    tn[2] = __fsub_rn(mq2, dot3_ref(ms0, ms1, ms2, Rf[2][0], Rf[2][1], Rf[2][2]));

    const float new_mse = __fdiv_rn(smu[6], (float)M);

    #pragma unroll
    for (int i = 0; i < 3; i++)
        #pragma unroll
        for (int j = 0; j < 3; j++)
            g_R[b][3 * i + j] = Rf[i][j];
    g_t[b][0] = tn[0]; g_t[b][1] = tn[1]; g_t[b][2] = tn[2];
    g_mse[b] = new_mse;
    if (new_mse < MSE_THRESH) g_done[b] = 1;
    __threadfence();   // publish pose for next iteration's blocks
}

// -------- write output: R (16,3,3) | t (16,3,1) | mse (16,1) --------
__global__ void writeout_kernel(float* __restrict__ out) {
    int i = threadIdx.x;
    if (i < 144) {
        out[i] = g_R[i / 9][i % 9];
    } else if (i < 192) {
        int k = i - 144;
        out[i] = g_t[k / 3][k % 3];
    } else if (i < 208) {
        out[i] = g_mse[i - 192];
    }
}

extern "C" void kernel_launch(void* const* d_in, const int* in_sizes, int n_in,
                              void* d_out, int out_size) {
    const float* src  = (const float*)d_in[0];
    const float* dest = (const float*)d_in[1];
    float* out = (float*)d_out;

    init_kernel<<<1, 256>>>();
    for (int it = 0; it < ITERS; it++) {
        nn_update_kernel<<<NBLK, NTHREADS>>>(src, dest, it);
    }
    writeout_kernel<<<1, 256>>>(out);
}

// round 14
// speedup vs baseline: 3.3370x; 3.3370x over previous
#include <cuda_runtime.h>
#include <math.h>
#include <stdint.h>

#define B 16
#define M 2048
#define BPB 4                   // src-blocks per batch (512 src each, 2/thread)
#define DSPLIT 16               // dest slices per src-block
#define DLEN (M / DSPLIT)       // 128 dest points per slice
#define NBLK (B * BPB * DSPLIT) // 1024 blocks
#define NTHREADS 256
#define UTHREADS 512
#define MSE_THRESH 1e-5f

// -------- persistent device state (no allocations allowed) --------
__device__ float  g_R[B][9];
__device__ float  g_t[B][3];
__device__ float  g_mse[B];
__device__ int    g_done[B];
__device__ float2 g_pair[B][M][DSPLIT];   // {partial best d2, idx bits} per slice

// K=3 contraction as dot_general lowers: ascending-k fma chain, exact first
// product (acc starts at 0): fma(a2,b2, fma(a1,b1, a0*b0)).
__device__ __forceinline__ float dot3_ref(float a0, float a1, float a2,
                                          float b0, float b1, float b2) {
    return fmaf(a2, b2, fmaf(a1, b1, __fmul_rn(a0, b0)));
}

// (v*v).sum as multiply+reduce lowers: rounded products, sequential adds, no fma
__device__ __forceinline__ float sqsum3(float x, float y, float z) {
    return __fadd_rn(__fadd_rn(__fmul_rn(x, x), __fmul_rn(y, y)), __fmul_rn(z, z));
}

// pairwise balanced tree over 8 lanes: offsets 1,2,4 ascending (FROZEN: R7 order)
__device__ __forceinline__ float tree8(float x) {
    x = __fadd_rn(x, __shfl_down_sync(0xffffffffu, x, 1));
    x = __fadd_rn(x, __shfl_down_sync(0xffffffffu, x, 2));
    x = __fadd_rn(x, __shfl_down_sync(0xffffffffu, x, 4));
    return x;
}

__device__ __forceinline__ unsigned long long pack2(float v) {
    unsigned int u = __float_as_uint(v);
    return ((unsigned long long)u << 32) | (unsigned long long)u;
}

// packed f32x2 ops: per-lane IEEE fp32, bit-identical to scalar sequence
__device__ __forceinline__ unsigned long long mul2(unsigned long long a, unsigned long long b) {
    unsigned long long d; asm("mul.rn.f32x2 %0, %1, %2;" : "=l"(d) : "l"(a), "l"(b)); return d;
}
__device__ __forceinline__ unsigned long long fma2(unsigned long long a, unsigned long long b,
                                                   unsigned long long c) {
    unsigned long long d; asm("fma.rn.f32x2 %0, %1, %2, %3;" : "=l"(d) : "l"(a), "l"(b), "l"(c)); return d;
}
__device__ __forceinline__ unsigned long long add2(unsigned long long a, unsigned long long b) {
    unsigned long long d; asm("add.rn.f32x2 %0, %1, %2;" : "=l"(d) : "l"(a), "l"(b)); return d;
}
__device__ __forceinline__ float lo32(unsigned long long v) { return __uint_as_float((unsigned int)v); }
__device__ __forceinline__ float hi32(unsigned long long v) { return __uint_as_float((unsigned int)(v >> 32)); }

__global__ void init_kernel() {
    int i = threadIdx.x;
    if (i < B) {
        #pragma unroll
        for (int k = 0; k < 9; k++) g_R[i][k] = (k % 4 == 0) ? 1.0f : 0.0f;
        g_t[i][0] = 0.f; g_t[i][1] = 0.f; g_t[i][2] = 0.f;
        g_mse[i] = 0.f;
        g_done[i] = 0;
    }
}

// -------- NN pass: 512 src (2/thread) x 128 dest per block, packed f32x2 --------
__global__ __launch_bounds__(NTHREADS)
void nn_kernel(const float* __restrict__ src,
               const float* __restrict__ dest) {
    __shared__ ulonglong2 qP[DLEN / 2];   // {x pair, y pair}
    __shared__ ulonglong2 qQ[DLEN / 2];   // {z pair, qq pair}

    const int bid = blockIdx.x;
    const int b   = bid / (BPB * DSPLIT);
    const int rem = bid % (BPB * DSPLIT);
    const int blk = rem / DSPLIT;
    const int d   = rem % DSPLIT;
    if (g_done[b]) return;

    const int tid  = threadIdx.x;
    const int jof  = d * DLEN;
    const float* db = dest + (size_t)b * 3 * M;
    const float* sb = src  + (size_t)b * 3 * M;

    if (tid < DLEN) {
        int jj = jof + tid;
        float x = db[jj], y = db[M + jj], z = db[2 * M + jj];
        float qq = sqsum3(x, y, z);
        float* fP = (float*)qP; float* fQ = (float*)qQ;
        int p = tid >> 1, o = tid & 1;
        fP[4 * p + o]     = x;  fP[4 * p + 2 + o] = y;
        fQ[4 * p + o]     = z;  fQ[4 * p + 2 + o] = qq;
    }

    float R0 = g_R[b][0], R1 = g_R[b][1], R2 = g_R[b][2];
    float R3 = g_R[b][3], R4 = g_R[b][4], R5 = g_R[b][5];
    float R6 = g_R[b][6], R7 = g_R[b][7], R8 = g_R[b][8];
    float t0 = g_t[b][0], t1 = g_t[b][1], t2 = g_t[b][2];

    __syncthreads();

    // two src points per thread
    const int mA = blk * (2 * NTHREADS) + tid;
    const int mB = mA + NTHREADS;
    unsigned long long pxA, pyA, pzA, ppA, pxB, pyB, pzB, ppB;
    {
        float sx = sb[mA], sy = sb[M + mA], sz = sb[2 * M + mA];
        float px = __fadd_rn(dot3_ref(sx, sy, sz, R0, R1, R2), t0);
        float py = __fadd_rn(dot3_ref(sx, sy, sz, R3, R4, R5), t1);
        float pz = __fadd_rn(dot3_ref(sx, sy, sz, R6, R7, R8), t2);
        float pp = sqsum3(px, py, pz);
        pxA = pack2(px); pyA = pack2(py); pzA = pack2(pz); ppA = pack2(pp);
    }
    {
        float sx = sb[mB], sy = sb[M + mB], sz = sb[2 * M + mB];
        float px = __fadd_rn(dot3_ref(sx, sy, sz, R0, R1, R2), t0);
        float py = __fadd_rn(dot3_ref(sx, sy, sz, R3, R4, R5), t1);
        float pz = __fadd_rn(dot3_ref(sx, sy, sz, R6, R7, R8), t2);
        float pp = sqsum3(px, py, pz);
        pxB = pack2(px); pyB = pack2(py); pzB = pack2(pz); ppB = pack2(pp);
    }
    const unsigned long long n2 = pack2(-2.0f);

    const float INF = __int_as_float(0x7f800000);
    float a0 = INF, a1 = INF, a2 = INF, a3 = INF;
    float c0 = INF, c1 = INF, c2 = INF, c3 = INF;
    int   ia0 = 0, ia1 = 0, ia2 = 0, ia3 = 0;
    int   ic0 = 0, ic1 = 0, ic2 = 0, ic3 = 0;

    #pragma unroll 4
    for (int j2 = 0; j2 < DLEN / 2; j2 += 2) {
        ulonglong2 A0 = qP[j2],     B0 = qQ[j2];
        ulonglong2 A1 = qP[j2 + 1], B1 = qQ[j2 + 1];
        int base = 2 * j2;
        {   // src A: per lane d2 = fma(-2, dot, pp+qq)
            unsigned long long dd0 = fma2(n2, fma2(pzA, B0.x, fma2(pyA, A0.y, mul2(pxA, A0.x))), add2(ppA, B0.y));
            unsigned long long dd1 = fma2(n2, fma2(pzA, B1.x, fma2(pyA, A1.y, mul2(pxA, A1.x))), add2(ppA, B1.y));
            float d0 = lo32(dd0), d1 = hi32(dd0), d2v = lo32(dd1), d3v = hi32(dd1);
            if (d0  < a0) { a0 = d0;  ia0 = base; }
            if (d1  < a1) { a1 = d1;  ia1 = base + 1; }
            if (d2v < a2) { a2 = d2v; ia2 = base + 2; }
            if (d3v < a3) { a3 = d3v; ia3 = base + 3; }
        }
        {   // src B
            unsigned long long dd0 = fma2(n2, fma2(pzB, B0.x, fma2(pyB, A0.y, mul2(pxB, A0.x))), add2(ppB, B0.y));
            unsigned long long dd1 = fma2(n2, fma2(pzB, B1.x, fma2(pyB, A1.y, mul2(pxB, A1.x))), add2(ppB, B1.y));
            float d0 = lo32(dd0), d1 = hi32(dd0), d2v = lo32(dd1), d3v = hi32(dd1);
            if (d0  < c0) { c0 = d0;  ic0 = base; }
            if (d1  < c1) { c1 = d1;  ic1 = base + 1; }
            if (d2v < c2) { c2 = d2v; ic2 = base + 2; }
            if (d3v < c3) { c3 = d3v; ic3 = base + 3; }
        }
    }

    {   // merge src A with exact first-min tie rule
        float best = a0; int bi = ia0;
        if (a1 < best || (a1 == best && ia1 < bi)) { best = a1; bi = ia1; }
        if (a2 < best || (a2 == best && ia2 < bi)) { best = a2; bi = ia2; }
        if (a3 < best || (a3 == best && ia3 < bi)) { best = a3; bi = ia3; }
        g_pair[b][mA][d] = make_float2(best, __int_as_float(jof + bi));
    }
    {   // merge src B
        float best = c0; int bi = ic0;
        if (c1 < best || (c1 == best && ic1 < bi)) { best = c1; bi = ic1; }
        if (c2 < best || (c2 == best && ic2 < bi)) { best = c2; bi = ic2; }
        if (c3 < best || (c3 == best && ic3 < bi)) { best = c3; bi = ic3; }
        g_pair[b][mB][d] = make_float2(best, __int_as_float(jof + bi));
    }
}

// -------- update: parallel merge/gather, serial FROZEN chains in smem, fp32 SVD --------
__global__ __launch_bounds__(UTHREADS) void update_kernel(const float* __restrict__ src,
                                                          const float* __restrict__ dest) {
    const int b = blockIdx.x;
    if (g_done[b]) return;

    __shared__ float4 P1[M];     // pass1 {w,wsx,wsy,wsz} -> pass2 {a0,a1,a2,-}
    __shared__ float4 P2[M];     // pass1 {wqx,wqy,wqz,nn} -> pass2 {c0,c1,c2,-}
    __shared__ int    six[M];
    __shared__ float  smu[8];

    const int tid = threadIdx.x;
    const float* sb = src  + (size_t)b * 3 * M;
    const float* db = dest + (size_t)b * 3 * M;

    // ---- pass1: merge 16 slice partials (vector loads) + phase-A products ----
    for (int m = tid; m < M; m += UTHREADS) {
        const float4* p4 = (const float4*)&g_pair[b][m][0];   // 8 x float4
        float4 f = p4[0];
        float best = f.x; int bi = __float_as_int(f.y);
        if (f.z < best) { best = f.z; bi = __float_as_int(f.w); }
        #pragma unroll
        for (int k = 1; k < 8; k++) {
            f = p4[k];
            if (f.x < best) { best = f.x; bi = __float_as_int(f.y); }
            if (f.z < best) { best = f.z; bi = __float_as_int(f.w); }
        }
        float nn = fmaxf(best, 0.0f);
        float w  = (sqrtf(nn) < 3.0f) ? 1.0f : 0.0f;
        float qx = db[bi], qy = db[M + bi], qz = db[2 * M + bi];
        P1[m] = make_float4(w,
                            __fmul_rn(w, sb[m]),
                            __fmul_rn(w, sb[M + m]),
                            __fmul_rn(w, sb[2 * M + m]));
        P2[m] = make_float4(__fmul_rn(w, qx),
                            __fmul_rn(w, qy),
                            __fmul_rn(w, qz),
                            nn);
        six[m] = bi;
    }
    __syncthreads();

    // ---- serial phase A: FROZEN add chains (warp 0, lanes 0-7) ----
    if (tid < 32) {
        const int lane = tid;
        float pw = 0.f, ps0 = 0.f, ps1 = 0.f, ps2 = 0.f;
        float pq0 = 0.f, pq1 = 0.f, pq2 = 0.f, pnn = 0.f;
        if (lane < 8) {
            for (int k = 0; k < M / 8; k++) {
                int m = lane + 8 * k;
                float4 a = P1[m];
                float4 c = P2[m];
                pw  = __fadd_rn(pw,  a.x);
                ps0 = __fadd_rn(ps0, a.y);
                ps1 = __fadd_rn(ps1, a.z);
                ps2 = __fadd_rn(ps2, a.w);
                pq0 = __fadd_rn(pq0, c.x);
                pq1 = __fadd_rn(pq1, c.y);
                pq2 = __fadd_rn(pq2, c.z);
                pnn = __fadd_rn(pnn, c.w);
            }
        }
        pw  = tree8(pw);
        ps0 = tree8(ps0); ps1 = tree8(ps1); ps2 = tree8(ps2);
        pq0 = tree8(pq0); pq1 = tree8(pq1); pq2 = tree8(pq2);
        pnn = tree8(pnn);
        if (lane == 0) {
            float wsum = __fadd_rn(pw, 1e-8f);
            smu[0] = __fdiv_rn(ps0, wsum);
            smu[1] = __fdiv_rn(ps1, wsum);
            smu[2] = __fdiv_rn(ps2, wsum);
            smu[3] = __fdiv_rn(pq0, wsum);
            smu[4] = __fdiv_rn(pq1, wsum);
            smu[5] = __fdiv_rn(pq2, wsum);
            smu[6] = pnn;
        }
    }
    __syncthreads();

    const float ms0 = smu[0], ms1 = smu[1], ms2 = smu[2];
    const float mq0 = smu[3], mq1 = smu[4], mq2 = smu[5];

    // ---- pass2: centered products (order-free), overwrite P1/P2 ----
    for (int m = tid; m < M; m += UTHREADS) {
        float w = P1[m].x;
        int   j = six[m];
        P1[m] = make_float4(__fmul_rn(__fsub_rn(sb[m],         ms0), w),
                            __fmul_rn(__fsub_rn(sb[M + m],     ms1), w),
                            __fmul_rn(__fsub_rn(sb[2 * M + m], ms2), w),
                            0.f);
        P2[m] = make_float4(__fsub_rn(db[j],         mq0),
                            __fsub_rn(db[M + j],     mq1),
                            __fsub_rn(db[2 * M + j], mq2),
                            0.f);
    }
    __syncthreads();

    if (tid >= 32) return;
    const int lane = tid;

    // ---- serial phase B: FROZEN fma chains (warp 0, lanes 0-7) ----
    float h[9] = {0,0,0,0,0,0,0,0,0};
    if (lane < 8) {
        for (int k = 0; k < M / 8; k++) {
            int m = lane + 8 * k;
            float4 a = P1[m];
            float4 c = P2[m];
            h[0] = fmaf(a.x, c.x, h[0]); h[1] = fmaf(a.x, c.y, h[1]); h[2] = fmaf(a.x, c.z, h[2]);
            h[3] = fmaf(a.y, c.x, h[3]); h[4] = fmaf(a.y, c.y, h[4]); h[5] = fmaf(a.y, c.z, h[5]);
            h[6] = fmaf(a.z, c.x, h[6]); h[7] = fmaf(a.z, c.y, h[7]); h[8] = fmaf(a.z, c.z, h[8]);
        }
    }
    #pragma unroll
    for (int v = 0; v < 9; v++) h[v] = tree8(h[v]);

    if (lane != 0) return;

    // ---- fp32 Jacobi SVD (unchanged from R10-R12) ----
    float Hf[3][3];
    #pragma unroll
    for (int v = 0; v < 9; v++) Hf[v / 3][v % 3] = h[v];

    float A[3][3];
    #pragma unroll
    for (int i = 0; i < 3; i++)
        #pragma unroll
        for (int j = 0; j < 3; j++)
            A[i][j] = fmaf(Hf[2][i], Hf[2][j], fmaf(Hf[1][i], Hf[1][j], Hf[0][i] * Hf[0][j]));

    const float tr = A[0][0] + A[1][1] + A[2][2];
    const float off_thr = 1e-12f * tr * tr;
    float V[3][3] = {{1,0,0},{0,1,0},{0,0,1}};
    for (int sweep = 0; sweep < 6; sweep++) {
        float off = A[0][1]*A[0][1] + A[0][2]*A[0][2] + A[1][2]*A[1][2];
        if (off <= off_thr) break;
        #pragma unroll
        for (int pi = 0; pi < 3; pi++) {
            int p = (pi == 2) ? 1 : 0;
            int q = (pi == 0) ? 1 : 2;
            float apq = A[p][q];
            if (fabsf(apq) < 1e-30f) continue;
            float theta = (A[q][q] - A[p][p]) / (2.0f * apq);
            float tt = copysignf(1.0f, theta) / (fabsf(theta) + sqrtf(fmaf(theta, theta, 1.0f)));
            float c = rsqrtf(fmaf(tt, tt, 1.0f));
            float s = tt * c;
            #pragma unroll
            for (int k = 0; k < 3; k++) {
                float akp = A[k][p], akq = A[k][q];
                A[k][p] = c * akp - s * akq;
                A[k][q] = s * akp + c * akq;
            }
            #pragma unroll
            for (int k = 0; k < 3; k++) {
                float apk = A[p][k], aqk = A[q][k];
                A[p][k] = c * apk - s * aqk;
                A[q][k] = s * apk + c * aqk;
            }
            #pragma unroll
            for (int k = 0; k < 3; k++) {
                float vkp = V[k][p], vkq = V[k][q];
                V[k][p] = c * vkp - s * vkq;
                V[k][q] = s * vkp + c * vkq;
            }
        }
    }

    float lam[3] = {A[0][0], A[1][1], A[2][2]};
    int idx[3] = {0, 1, 2};
    #pragma unroll
    for (int i = 0; i < 2; i++)
        #pragma unroll
        for (int j = i + 1; j < 3; j++)
            if (lam[idx[j]] > lam[idx[i]]) { int t = idx[i]; idx[i] = idx[j]; idx[j] = t; }

    float detH = Hf[0][0]*(Hf[1][1]*Hf[2][2]-Hf[1][2]*Hf[2][1])
               - Hf[0][1]*(Hf[1][0]*Hf[2][2]-Hf[1][2]*Hf[2][0])
               + Hf[0][2]*(Hf[1][0]*Hf[2][1]-Hf[1][1]*Hf[2][0]);
    float d3 = (detH >= 0.0f) ? 1.0f : -1.0f;

    float coef[3], Vs[3][3];
    #pragma unroll
    for (int r = 0; r < 3; r++) {
        float sv = sqrtf(fmaxf(lam[idx[r]], 0.0f));
        float dr = (r == 2) ? d3 : 1.0f;
        coef[r] = (sv > 1e-20f) ? (dr / sv) : 0.0f;
        #pragma unroll
        for (int k = 0; k < 3; k++) Vs[k][r] = V[k][idx[r]];
    }

    float M2[3][3];
    #pragma unroll
    for (int i = 0; i < 3; i++)
        #pragma unroll
        for (int j = 0; j < 3; j++)
            M2[i][j] = fmaf(Vs[i][2] * coef[2], Vs[j][2],
                       fmaf(Vs[i][1] * coef[1], Vs[j][1],
                            Vs[i][0] * coef[0] * Vs[j][0]));
    float Rf[3][3];
    #pragma unroll
    for (int i = 0; i < 3; i++)
        #pragma unroll
        for (int j = 0; j < 3; j++)
            Rf[i][j] = fmaf(M2[i][2], Hf[j][2],
                       fmaf(M2[i][1], Hf[j][1],
                            M2[i][0] * Hf[j][0]));

    float tn[3];
    tn[0] = __fsub_rn(mq0, dot3_ref(ms0, ms1, ms2, Rf[0][0], Rf[0][1], Rf[0][2]));
    tn[1] = __fsub_rn(mq1, dot3_ref(ms0, ms1, ms2, Rf[1][0], Rf[1][1], Rf[1][2]));
    tn[2] = __fsub_rn(mq2, dot3_ref(ms0, ms1, ms2, Rf[2][0], Rf[2][1], Rf[2][2]));

    const float new_mse = __fdiv_rn(smu[6], (float)M);

    #pragma unroll
    for (int i = 0; i < 3; i++)
        #pragma unroll
        for (int j = 0; j < 3; j++)
            g_R[b][3 * i + j] = Rf[i][j];
    g_t[b][0] = tn[0]; g_t[b][1] = tn[1]; g_t[b][2] = tn[2];
    g_mse[b] = new_mse;
    if (new_mse < MSE_THRESH) g_done[b] = 1;
}

// -------- write output: R (16,3,3) | t (16,3,1) | mse (16,1) --------
__global__ void writeout_kernel(float* __restrict__ out) {
    int i = threadIdx.x;
    if (i < 144) {
        out[i] = g_R[i / 9][i % 9];
    } else if (i < 192) {
        int k = i - 144;
        out[i] = g_t[k / 3][k % 3];
    } else if (i < 208) {
        out[i] = g_mse[i - 192];
    }
}

extern "C" void kernel_launch(void* const* d_in, const int* in_sizes, int n_in,
                              void* d_out, int out_size) {
    const float* src  = (const float*)d_in[0];
    const float* dest = (const float*)d_in[1];
    float* out = (float*)d_out;

    init_kernel<<<1, 32>>>();
    for (int it = 0; it < 10; it++) {
        nn_kernel<<<NBLK, NTHREADS>>>(src, dest);
        update_kernel<<<B, UTHREADS>>>(src, dest);
    }
    writeout_kernel<<<1, 256>>>(out);
}

// round 15
// speedup vs baseline: 3.5614x; 1.0673x over previous
#include <cuda_runtime.h>
#include <math.h>
#include <stdint.h>

#define B 16
#define M 2048
#define BPB 4                   // src-blocks per batch (512 src each, 2/thread)
#define DSPLIT 16               // dest slices per src-block
#define DLEN (M / DSPLIT)       // 128 dest points per slice
#define NBLK (B * BPB * DSPLIT) // 1024 blocks
#define NTHREADS 256
#define UTHREADS 512
#define MSE_THRESH 1e-5f

// -------- persistent device state (no allocations allowed) --------
__device__ float  g_R[B][9];
__device__ float  g_t[B][3];
__device__ float  g_mse[B];
__device__ int    g_done[B];
__device__ float2 g_pair[B][M][DSPLIT];   // {partial best d2, idx bits} per slice

// K=3 contraction as dot_general lowers: ascending-k fma chain, exact first
// product (acc starts at 0): fma(a2,b2, fma(a1,b1, a0*b0)).
__device__ __forceinline__ float dot3_ref(float a0, float a1, float a2,
                                          float b0, float b1, float b2) {
    return fmaf(a2, b2, fmaf(a1, b1, __fmul_rn(a0, b0)));
}

// (v*v).sum as multiply+reduce lowers: rounded products, sequential adds, no fma
__device__ __forceinline__ float sqsum3(float x, float y, float z) {
    return __fadd_rn(__fadd_rn(__fmul_rn(x, x), __fmul_rn(y, y)), __fmul_rn(z, z));
}

// pairwise balanced tree over 8 lanes: offsets 1,2,4 ascending (FROZEN: R7 order)
__device__ __forceinline__ float tree8(float x) {
    x = __fadd_rn(x, __shfl_down_sync(0xffffffffu, x, 1));
    x = __fadd_rn(x, __shfl_down_sync(0xffffffffu, x, 2));
    x = __fadd_rn(x, __shfl_down_sync(0xffffffffu, x, 4));
    return x;
}

__device__ __forceinline__ unsigned long long pack2(float v) {
    unsigned int u = __float_as_uint(v);
    return ((unsigned long long)u << 32) | (unsigned long long)u;
}

// packed f32x2 ops: per-lane IEEE fp32, bit-identical to scalar sequence
__device__ __forceinline__ unsigned long long mul2(unsigned long long a, unsigned long long b) {
    unsigned long long d; asm("mul.rn.f32x2 %0, %1, %2;" : "=l"(d) : "l"(a), "l"(b)); return d;
}
__device__ __forceinline__ unsigned long long fma2(unsigned long long a, unsigned long long b,
                                                   unsigned long long c) {
    unsigned long long d; asm("fma.rn.f32x2 %0, %1, %2, %3;" : "=l"(d) : "l"(a), "l"(b), "l"(c)); return d;
}
__device__ __forceinline__ unsigned long long add2(unsigned long long a, unsigned long long b) {
    unsigned long long d; asm("add.rn.f32x2 %0, %1, %2;" : "=l"(d) : "l"(a), "l"(b)); return d;
}
__device__ __forceinline__ float lo32(unsigned long long v) { return __uint_as_float((unsigned int)v); }
__device__ __forceinline__ float hi32(unsigned long long v) { return __uint_as_float((unsigned int)(v >> 32)); }

__global__ void init_kernel() {
    int i = threadIdx.x;
    if (i < B) {
        #pragma unroll
        for (int k = 0; k < 9; k++) g_R[i][k] = (k % 4 == 0) ? 1.0f : 0.0f;
        g_t[i][0] = 0.f; g_t[i][1] = 0.f; g_t[i][2] = 0.f;
        g_mse[i] = 0.f;
        g_done[i] = 0;
    }
}

// scalar d2, bit-identical to one lane of the packed pipeline
__device__ __forceinline__ float d2_scalar(float px, float py, float pz, float pp,
                                           float x, float y, float z, float qq) {
    return fmaf(-2.0f, fmaf(pz, z, fmaf(py, y, __fmul_rn(px, x))), __fadd_rn(pp, qq));
}

// -------- NN pass: 512 src (2/thread) x 128 dest per block, block-min argmin --------
__global__ __launch_bounds__(NTHREADS)
void nn_kernel(const float* __restrict__ src,
               const float* __restrict__ dest) {
    __shared__ ulonglong2 qP[DLEN / 2];   // {x pair, y pair}
    __shared__ ulonglong2 qQ[DLEN / 2];   // {z pair, qq pair}

    const int bid = blockIdx.x;
    const int b   = bid / (BPB * DSPLIT);
    const int rem = bid % (BPB * DSPLIT);
    const int blk = rem / DSPLIT;
    const int d   = rem % DSPLIT;
    if (g_done[b]) return;

    const int tid  = threadIdx.x;
    const int jof  = d * DLEN;
    const float* db = dest + (size_t)b * 3 * M;
    const float* sb = src  + (size_t)b * 3 * M;

    if (tid < DLEN) {
        int jj = jof + tid;
        float x = db[jj], y = db[M + jj], z = db[2 * M + jj];
        float qq = sqsum3(x, y, z);
        float* fP = (float*)qP; float* fQ = (float*)qQ;
        int p = tid >> 1, o = tid & 1;
        fP[4 * p + o]     = x;  fP[4 * p + 2 + o] = y;
        fQ[4 * p + o]     = z;  fQ[4 * p + 2 + o] = qq;
    }

    float R0 = g_R[b][0], R1 = g_R[b][1], R2 = g_R[b][2];
    float R3 = g_R[b][3], R4 = g_R[b][4], R5 = g_R[b][5];
    float R6 = g_R[b][6], R7 = g_R[b][7], R8 = g_R[b][8];
    float t0 = g_t[b][0], t1 = g_t[b][1], t2 = g_t[b][2];

    __syncthreads();

    // two src points per thread
    const int mA = blk * (2 * NTHREADS) + tid;
    const int mB = mA + NTHREADS;
    float pxAs, pyAs, pzAs, ppAs, pxBs, pyBs, pzBs, ppBs;
    {
        float sx = sb[mA], sy = sb[M + mA], sz = sb[2 * M + mA];
        pxAs = __fadd_rn(dot3_ref(sx, sy, sz, R0, R1, R2), t0);
        pyAs = __fadd_rn(dot3_ref(sx, sy, sz, R3, R4, R5), t1);
        pzAs = __fadd_rn(dot3_ref(sx, sy, sz, R6, R7, R8), t2);
        ppAs = sqsum3(pxAs, pyAs, pzAs);
    }
    {
        float sx = sb[mB], sy = sb[M + mB], sz = sb[2 * M + mB];
        pxBs = __fadd_rn(dot3_ref(sx, sy, sz, R0, R1, R2), t0);
        pyBs = __fadd_rn(dot3_ref(sx, sy, sz, R3, R4, R5), t1);
        pzBs = __fadd_rn(dot3_ref(sx, sy, sz, R6, R7, R8), t2);
        ppBs = sqsum3(pxBs, pyBs, pzBs);
    }
    const unsigned long long pxA = pack2(pxAs), pyA = pack2(pyAs), pzA = pack2(pzAs), ppA = pack2(ppAs);
    const unsigned long long pxB = pack2(pxBs), pyB = pack2(pyBs), pzB = pack2(pzBs), ppB = pack2(ppBs);
    const unsigned long long n2 = pack2(-2.0f);

    const float INF = __int_as_float(0x7f800000);
    float bestA = INF, bestB = INF;
    int   jbA   = 0,   jbB   = 0;     // winning 4-dest block base

    #pragma unroll 4
    for (int j2 = 0; j2 < DLEN / 2; j2 += 2) {
        ulonglong2 A0 = qP[j2],     B0 = qQ[j2];
        ulonglong2 A1 = qP[j2 + 1], B1 = qQ[j2 + 1];
        int base = 2 * j2;
        {   // src A: packed d2 for 4 dest, then 4-wide min
            unsigned long long dd0 = fma2(n2, fma2(pzA, B0.x, fma2(pyA, A0.y, mul2(pxA, A0.x))), add2(ppA, B0.y));
            unsigned long long dd1 = fma2(n2, fma2(pzA, B1.x, fma2(pyA, A1.y, mul2(pxA, A1.x))), add2(ppA, B1.y));
            float bm = fminf(fminf(lo32(dd0), hi32(dd0)), fminf(lo32(dd1), hi32(dd1)));
            if (bm < bestA) { bestA = bm; jbA = base; }   // strict <: earliest block on tie
        }
        {   // src B
            unsigned long long dd0 = fma2(n2, fma2(pzB, B0.x, fma2(pyB, A0.y, mul2(pxB, A0.x))), add2(ppB, B0.y));
            unsigned long long dd1 = fma2(n2, fma2(pzB, B1.x, fma2(pyB, A1.y, mul2(pxB, A1.x))), add2(ppB, B1.y));
            float bm = fminf(fminf(lo32(dd0), hi32(dd0)), fminf(lo32(dd1), hi32(dd1)));
            if (bm < bestB) { bestB = bm; jbB = base; }
        }
    }

    {   // src A tail: rescan winning block, first index with d2 == best
        int j2 = jbA >> 1;
        ulonglong2 A0 = qP[j2], B0 = qQ[j2], A1 = qP[j2 + 1], B1 = qQ[j2 + 1];
        float d0 = d2_scalar(pxAs, pyAs, pzAs, ppAs, lo32(A0.x), lo32(A0.y), lo32(B0.x), lo32(B0.y));
        float d1 = d2_scalar(pxAs, pyAs, pzAs, ppAs, hi32(A0.x), hi32(A0.y), hi32(B0.x), hi32(B0.y));
        float d2v = d2_scalar(pxAs, pyAs, pzAs, ppAs, lo32(A1.x), lo32(A1.y), lo32(B1.x), lo32(B1.y));
        int bi;
        if      (d0  == bestA) bi = jbA;
        else if (d1  == bestA) bi = jbA + 1;
        else if (d2v == bestA) bi = jbA + 2;
        else                   bi = jbA + 3;
        g_pair[b][mA][d] = make_float2(bestA, __int_as_float(jof + bi));
    }
    {   // src B tail
        int j2 = jbB >> 1;
        ulonglong2 A0 = qP[j2], B0 = qQ[j2], A1 = qP[j2 + 1], B1 = qQ[j2 + 1];
        float d0 = d2_scalar(pxBs, pyBs, pzBs, ppBs, lo32(A0.x), lo32(A0.y), lo32(B0.x), lo32(B0.y));
        float d1 = d2_scalar(pxBs, pyBs, pzBs, ppBs, hi32(A0.x), hi32(A0.y), hi32(B0.x), hi32(B0.y));
        float d2v = d2_scalar(pxBs, pyBs, pzBs, ppBs, lo32(A1.x), lo32(A1.y), lo32(B1.x), lo32(B1.y));
        int bi;
        if      (d0  == bestB) bi = jbB;
        else if (d1  == bestB) bi = jbB + 1;
        else if (d2v == bestB) bi = jbB + 2;
        else                   bi = jbB + 3;
        g_pair[b][mB][d] = make_float2(bestB, __int_as_float(jof + bi));
    }
}

// -------- update: parallel merge/gather, 2-warp FROZEN chains, fp32 SVD --------
__global__ __launch_bounds__(UTHREADS) void update_kernel(const float* __restrict__ src,
                                                          const float* __restrict__ dest) {
    const int b = blockIdx.x;
    if (g_done[b]) return;

    __shared__ float4 P1[M];     // pass1 {w,wsx,wsy,wsz} -> pass2 {a0,a1,a2,-}
    __shared__ float4 P2[M];     // pass1 {wqx,wqy,wqz,nn} -> pass2 {c0,c1,c2,-}
    __shared__ int    six[M];
    __shared__ float  smu[8];
    __shared__ float  shh[9];

    const int tid = threadIdx.x;
    const float* sb = src  + (size_t)b * 3 * M;
    const float* db = dest + (size_t)b * 3 * M;

    // ---- pass1: merge 16 slice partials (vector loads) + phase-A products ----
    for (int m = tid; m < M; m += UTHREADS) {
        const float4* p4 = (const float4*)&g_pair[b][m][0];   // 8 x float4
        float4 f = p4[0];
        float best = f.x; int bi = __float_as_int(f.y);
        if (f.z < best) { best = f.z; bi = __float_as_int(f.w); }
        #pragma unroll
        for (int k = 1; k < 8; k++) {
            f = p4[k];
            if (f.x < best) { best = f.x; bi = __float_as_int(f.y); }
            if (f.z < best) { best = f.z; bi = __float_as_int(f.w); }
        }
        float nn = fmaxf(best, 0.0f);
        float w  = (sqrtf(nn) < 3.0f) ? 1.0f : 0.0f;
        float qx = db[bi], qy = db[M + bi], qz = db[2 * M + bi];
        P1[m] = make_float4(w,
                            __fmul_rn(w, sb[m]),
                            __fmul_rn(w, sb[M + m]),
                            __fmul_rn(w, sb[2 * M + m]));
        P2[m] = make_float4(__fmul_rn(w, qx),
                            __fmul_rn(w, qy),
                            __fmul_rn(w, qz),
                            nn);
        six[m] = bi;
    }
    __syncthreads();

    // ---- phase A: FROZEN add chains, split across 2 warps ----
    if (tid < 64) {
        const int warp = tid >> 5, lane = tid & 31;
        if (warp == 0) {
            float pw = 0.f, ps0 = 0.f, ps1 = 0.f, ps2 = 0.f;
            if (lane < 8) {
                for (int k = 0; k < M / 8; k++) {
                    float4 a = P1[lane + 8 * k];
                    pw  = __fadd_rn(pw,  a.x);
                    ps0 = __fadd_rn(ps0, a.y);
                    ps1 = __fadd_rn(ps1, a.z);
                    ps2 = __fadd_rn(ps2, a.w);
                }
            }
            pw  = tree8(pw);
            ps0 = tree8(ps0); ps1 = tree8(ps1); ps2 = tree8(ps2);
            if (lane == 0) {
                float wsum = __fadd_rn(pw, 1e-8f);
                smu[0] = __fdiv_rn(ps0, wsum);
                smu[1] = __fdiv_rn(ps1, wsum);
                smu[2] = __fdiv_rn(ps2, wsum);
                smu[7] = wsum;
            }
        } else {
            float pq0 = 0.f, pq1 = 0.f, pq2 = 0.f, pnn = 0.f;
            if (lane < 8) {
                for (int k = 0; k < M / 8; k++) {
                    float4 c = P2[lane + 8 * k];
                    pq0 = __fadd_rn(pq0, c.x);
                    pq1 = __fadd_rn(pq1, c.y);
                    pq2 = __fadd_rn(pq2, c.z);
                    pnn = __fadd_rn(pnn, c.w);
                }
            }
            pq0 = tree8(pq0); pq1 = tree8(pq1); pq2 = tree8(pq2);
            pnn = tree8(pnn);
            if (lane == 0) {
                smu[3] = pq0;   // divided below (needs wsum from warp 0)
                smu[4] = pq1;
                smu[5] = pq2;
                smu[6] = pnn;
            }
        }
    }
    __syncthreads();
    if (tid == 0) {
        float wsum = smu[7];
        smu[3] = __fdiv_rn(smu[3], wsum);
        smu[4] = __fdiv_rn(smu[4], wsum);
        smu[5] = __fdiv_rn(smu[5], wsum);
    }
    __syncthreads();

    const float ms0 = smu[0], ms1 = smu[1], ms2 = smu[2];
    const float mq0 = smu[3], mq1 = smu[4], mq2 = smu[5];

    // ---- pass2: centered products (order-free), overwrite P1/P2 ----
    for (int m = tid; m < M; m += UTHREADS) {
        float w = P1[m].x;
        int   j = six[m];
        P1[m] = make_float4(__fmul_rn(__fsub_rn(sb[m],         ms0), w),
                            __fmul_rn(__fsub_rn(sb[M + m],     ms1), w),
                            __fmul_rn(__fsub_rn(sb[2 * M + m], ms2), w),
                            0.f);
        P2[m] = make_float4(__fsub_rn(db[j],         mq0),
                            __fsub_rn(db[M + j],     mq1),
                            __fsub_rn(db[2 * M + j], mq2),
                            0.f);
    }
    __syncthreads();

    // ---- phase B: FROZEN fma chains, 9 chains split across 2 warps ----
    if (tid < 64) {
        const int warp = tid >> 5, lane = tid & 31;
        if (warp == 0) {
            float h0 = 0, h1 = 0, h2 = 0, h3 = 0, h4 = 0;
            if (lane < 8) {
                for (int k = 0; k < M / 8; k++) {
                    int m = lane + 8 * k;
                    float4 a = P1[m];
                    float4 c = P2[m];
                    h0 = fmaf(a.x, c.x, h0); h1 = fmaf(a.x, c.y, h1); h2 = fmaf(a.x, c.z, h2);
                    h3 = fmaf(a.y, c.x, h3); h4 = fmaf(a.y, c.y, h4);
                }
            }
            h0 = tree8(h0); h1 = tree8(h1); h2 = tree8(h2); h3 = tree8(h3); h4 = tree8(h4);
            if (lane == 0) { shh[0] = h0; shh[1] = h1; shh[2] = h2; shh[3] = h3; shh[4] = h4; }
        } else {
            float h5 = 0, h6 = 0, h7 = 0, h8 = 0;
            if (lane < 8) {
                for (int k = 0; k < M / 8; k++) {
                    int m = lane + 8 * k;
                    float4 a = P1[m];
                    float4 c = P2[m];
                    h5 = fmaf(a.y, c.z, h5);
                    h6 = fmaf(a.z, c.x, h6); h7 = fmaf(a.z, c.y, h7); h8 = fmaf(a.z, c.z, h8);
                }
            }
            h5 = tree8(h5); h6 = tree8(h6); h7 = tree8(h7); h8 = tree8(h8);
            if (lane == 0) { shh[5] = h5; shh[6] = h6; shh[7] = h7; shh[8] = h8; }
        }
    }
    __syncthreads();

    if (tid != 0) return;

    // ---- fp32 Jacobi SVD (unchanged from R10-R14) ----
    float Hf[3][3];
    #pragma unroll
    for (int v = 0; v < 9; v++) Hf[v / 3][v % 3] = shh[v];

    float A[3][3];
    #pragma unroll
    for (int i = 0; i < 3; i++)
        #pragma unroll
        for (int j = 0; j < 3; j++)
            A[i][j] = fmaf(Hf[2][i], Hf[2][j], fmaf(Hf[1][i], Hf[1][j], Hf[0][i] * Hf[0][j]));

    const float tr = A[0][0] + A[1][1] + A[2][2];
    const float off_thr = 1e-12f * tr * tr;
    float V[3][3] = {{1,0,0},{0,1,0},{0,0,1}};
    for (int sweep = 0; sweep < 6; sweep++) {
        float off = A[0][1]*A[0][1] + A[0][2]*A[0][2] + A[1][2]*A[1][2];
        if (off <= off_thr) break;
        #pragma unroll
        for (int pi = 0; pi < 3; pi++) {
            int p = (pi == 2) ? 1 : 0;
            int q = (pi == 0) ? 1 : 2;
            float apq = A[p][q];
            if (fabsf(apq) < 1e-30f) continue;
            float theta = (A[q][q] - A[p][p]) / (2.0f * apq);
            float tt = copysignf(1.0f, theta) / (fabsf(theta) + sqrtf(fmaf(theta, theta, 1.0f)));
            float c = rsqrtf(fmaf(tt, tt, 1.0f));
            float s = tt * c;
            #pragma unroll
            for (int k = 0; k < 3; k++) {
                float akp = A[k][p], akq = A[k][q];
                A[k][p] = c * akp - s * akq;
                A[k][q] = s * akp + c * akq;
            }
            #pragma unroll
            for (int k = 0; k < 3; k++) {
                float apk = A[p][k], aqk = A[q][k];
                A[p][k] = c * apk - s * aqk;
                A[q][k] = s * apk + c * aqk;
            }
            #pragma unroll
            for (int k = 0; k < 3; k++) {
                float vkp = V[k][p], vkq = V[k][q];
                V[k][p] = c * vkp - s * vkq;
                V[k][q] = s * vkp + c * vkq;
            }
        }
    }

    float lam[3] = {A[0][0], A[1][1], A[2][2]};
    int idx[3] = {0, 1, 2};
    #pragma unroll
    for (int i = 0; i < 2; i++)
        #pragma unroll
        for (int j = i + 1; j < 3; j++)
            if (lam[idx[j]] > lam[idx[i]]) { int t = idx[i]; idx[i] = idx[j]; idx[j] = t; }

    float detH = Hf[0][0]*(Hf[1][1]*Hf[2][2]-Hf[1][2]*Hf[2][1])
               - Hf[0][1]*(Hf[1][0]*Hf[2][2]-Hf[1][2]*Hf[2][0])
               + Hf[0][2]*(Hf[1][0]*Hf[2][1]-Hf[1][1]*Hf[2][0]);
    float d3 = (detH >= 0.0f) ? 1.0f : -1.0f;

    float coef[3], Vs[3][3];
    #pragma unroll
    for (int r = 0; r < 3; r++) {
        float sv = sqrtf(fmaxf(lam[idx[r]], 0.0f));
        float dr = (r == 2) ? d3 : 1.0f;
        coef[r] = (sv > 1e-20f) ? (dr / sv) : 0.0f;
        #pragma unroll
        for (int k = 0; k < 3; k++) Vs[k][r] = V[k][idx[r]];
    }

    float M2[3][3];
    #pragma unroll
    for (int i = 0; i < 3; i++)
        #pragma unroll
        for (int j = 0; j < 3; j++)
            M2[i][j] = fmaf(Vs[i][2] * coef[2], Vs[j][2],
                       fmaf(Vs[i][1] * coef[1], Vs[j][1],
                            Vs[i][0] * coef[0] * Vs[j][0]));
    float Rf[3][3];
    #pragma unroll
    for (int i = 0; i < 3; i++)
        #pragma unroll
        for (int j = 0; j < 3; j++)
            Rf[i][j] = fmaf(M2[i][2], Hf[j][2],
                       fmaf(M2[i][1], Hf[j][1],
                            M2[i][0] * Hf[j][0]));

    float tn[3];
    tn[0] = __fsub_rn(mq0, dot3_ref(ms0, ms1, ms2, Rf[0][0], Rf[0][1], Rf[0][2]));
    tn[1] = __fsub_rn(mq1, dot3_ref(ms0, ms1, ms2, Rf[1][0], Rf[1][1], Rf[1][2]));
    tn[2] = __fsub_rn(mq2, dot3_ref(ms0, ms1, ms2, Rf[2][0], Rf[2][1], Rf[2][2]));

    const float new_mse = __fdiv_rn(smu[6], (float)M);

    #pragma unroll
    for (int i = 0; i < 3; i++)
        #pragma unroll
        for (int j = 0; j < 3; j++)
            g_R[b][3 * i + j] = Rf[i][j];
    g_t[b][0] = tn[0]; g_t[b][1] = tn[1]; g_t[b][2] = tn[2];
    g_mse[b] = new_mse;
    if (new_mse < MSE_THRESH) g_done[b] = 1;
}

// -------- write output: R (16,3,3) | t (16,3,1) | mse (16,1) --------
__global__ void writeout_kernel(float* __restrict__ out) {
    int i = threadIdx.x;
    if (i < 144) {
        out[i] = g_R[i / 9][i % 9];
    } else if (i < 192) {
        int k = i - 144;
        out[i] = g_t[k / 3][k % 3];
    } else if (i < 208) {
        out[i] = g_mse[i - 192];
    }
}

extern "C" void kernel_launch(void* const* d_in, const int* in_sizes, int n_in,
                              void* d_out, int out_size) {
    const float* src  = (const float*)d_in[0];
    const float* dest = (const float*)d_in[1];
    float* out = (float*)d_out;

    init_kernel<<<1, 32>>>();
    for (int it = 0; it < 10; it++) {
        nn_kernel<<<NBLK, NTHREADS>>>(src, dest);
        update_kernel<<<B, UTHREADS>>>(src, dest);
    }
    writeout_kernel<<<1, 256>>>(out);
}